// round 3
// baseline (speedup 1.0000x reference)
#include <cuda_runtime.h>
#include <math.h>

// Problem constants
#define NB 32
#define NS 1024
#define NT 256
#define NBS 32768          // NB*NS rows
#define NCAT 1024          // 4*NT concatenated transition columns

// Static device scratch (allocation-free rule: __device__ globals)
__device__ float g_P[NBS * NT];        // softmax(q)            33.5 MB
__device__ float g_Y[NBS * NCAT];      // P @ Tcat             134.2 MB
__device__ float g_Tcat[NT * NCAT];    // [T0 | T1 | T0^T | T1^T]  1 MB

// ---------------------------------------------------------------------------
// Build Tcat[k][n], k in [0,256), n in [0,1024)
//   n in [0,256):    T0[k][n]
//   n in [256,512):  T1[k][n-256]
//   n in [512,768):  T0[n-512][k]   (T0^T)
//   n in [768,1024): T1[n-768][k]   (T1^T)
// transitions layout: [2, 256, 256] row-major
// ---------------------------------------------------------------------------
__global__ void build_tcat_kernel(const float* __restrict__ trans) {
    int idx = blockIdx.x * blockDim.x + threadIdx.x;   // 0 .. 262143
    int k = idx >> 10;
    int n = idx & 1023;
    float v;
    if (n < 256)       v = trans[k * 256 + n];
    else if (n < 512)  v = trans[65536 + k * 256 + (n - 256)];
    else if (n < 768)  v = trans[(n - 512) * 256 + k];
    else               v = trans[65536 + (n - 768) * 256 + k];
    g_Tcat[idx] = v;
}

// ---------------------------------------------------------------------------
// SGEMM: g_Y[32768,1024] = g_P[32768,256] @ g_Tcat[256,1024]
// BM=128, BN=128, BK=8, 256 threads, each thread computes 8x8.
// ---------------------------------------------------------------------------
__global__ void __launch_bounds__(256) sgemm_kernel() {
    const int BM = 128, BN = 128, BK = 8;
    __shared__ float As[BK][BM];   // transposed A tile
    __shared__ float Bs[BK][BN];

    int tid = threadIdx.x;
    int blockRow = blockIdx.y * BM;
    int blockCol = blockIdx.x * BN;

    int threadRow = (tid / 16) * 8;       // 0,8,...,120
    int threadCol = (tid % 16) * 8;       // 0,8,...,120

    int innerRowA = tid / 2;              // 0..127
    int innerColA = (tid % 2) * 4;        // 0 or 4
    int innerRowB = tid / 32;             // 0..7
    int innerColB = (tid % 32) * 4;       // 0..124

    const float* Aptr = g_P + (blockRow + innerRowA) * NT + innerColA;
    const float* Bptr = g_Tcat + innerRowB * NCAT + blockCol + innerColB;

    float acc[8][8];
#pragma unroll
    for (int i = 0; i < 8; i++)
#pragma unroll
        for (int j = 0; j < 8; j++) acc[i][j] = 0.0f;

    for (int k0 = 0; k0 < NT; k0 += BK) {
        float4 av = *(const float4*)(Aptr + k0);
        As[innerColA + 0][innerRowA] = av.x;
        As[innerColA + 1][innerRowA] = av.y;
        As[innerColA + 2][innerRowA] = av.z;
        As[innerColA + 3][innerRowA] = av.w;
        *(float4*)&Bs[innerRowB][innerColB] = *(const float4*)(Bptr + k0 * NCAT);
        __syncthreads();

#pragma unroll
        for (int k = 0; k < BK; k++) {
            float rm[8], rn[8];
            float4 a0 = *(const float4*)&As[k][threadRow];
            float4 a1 = *(const float4*)&As[k][threadRow + 4];
            rm[0] = a0.x; rm[1] = a0.y; rm[2] = a0.z; rm[3] = a0.w;
            rm[4] = a1.x; rm[5] = a1.y; rm[6] = a1.z; rm[7] = a1.w;
            float4 b0 = *(const float4*)&Bs[k][threadCol];
            float4 b1 = *(const float4*)&Bs[k][threadCol + 4];
            rn[0] = b0.x; rn[1] = b0.y; rn[2] = b0.z; rn[3] = b0.w;
            rn[4] = b1.x; rn[5] = b1.y; rn[6] = b1.z; rn[7] = b1.w;
#pragma unroll
            for (int i = 0; i < 8; i++)
#pragma unroll
                for (int j = 0; j < 8; j++)
                    acc[i][j] += rm[i] * rn[j];
        }
        __syncthreads();
    }

    float* Yrow = g_Y + (size_t)(blockRow + threadRow) * NCAT + blockCol + threadCol;
#pragma unroll
    for (int i = 0; i < 8; i++) {
#pragma unroll
        for (int j = 0; j < 8; j += 4) {
            float4 v = make_float4(acc[i][j], acc[i][j + 1], acc[i][j + 2], acc[i][j + 3]);
            *(float4*)(Yrow + (size_t)i * NCAT + j) = v;
        }
    }
}

// ---------------------------------------------------------------------------
// Combine + softmax kernel. One block per (b,s) row, 256 threads (one per tag).
// mode 0: q = unary_score*mask (initial), then softmax -> g_P
// mode 1: q = (unary_score*mask + shifts(g_Y) + boundary)*mask, softmax -> g_P
// mode 2: same q, write q to out (final iteration)
// ---------------------------------------------------------------------------
__global__ void __launch_bounds__(256) combine_kernel(
    const float* __restrict__ unary_score,
    const float* __restrict__ mask,
    const float* __restrict__ start_t,   // [2,256]
    const float* __restrict__ end_t,     // [2,256]
    const int*   __restrict__ lengths,   // [32]
    float* __restrict__ out,
    int mode)
{
    int row = blockIdx.x;       // b*NS + s
    int t   = threadIdx.x;      // tag
    int b   = row >> 10;
    int s   = row & 1023;

    float m = mask[row];
    float u = unary_score[row * NT + t] * m;
    float qv;

    if (mode == 0) {
        qv = u;
    } else {
        float msg = 0.0f;
        if (s >= 1)      msg += g_Y[(size_t)(row - 1) * NCAT + t];          // left  j=1 (T0)
        if (s >= 2)      msg += g_Y[(size_t)(row - 2) * NCAT + 256 + t];    // left  j=2 (T1)
        if (s <= NS - 2) msg += g_Y[(size_t)(row + 1) * NCAT + 512 + t];    // right j=1 (T0^T)
        if (s <= NS - 3) msg += g_Y[(size_t)(row + 2) * NCAT + 768 + t];    // right j=2 (T1^T)
        int len = lengths[b];
        if (s == len - 1) msg += end_t[t];
        if (s == len - 2) msg += end_t[256 + t];
        if (s < 2)        msg += start_t[s * 256 + t];
        qv = (u + msg) * m;
    }

    if (mode == 2) {
        out[row * NT + t] = qv;
        return;
    }

    // Block softmax over 256 values
    __shared__ float red_max[8];
    __shared__ float red_sum[8];
    __shared__ float bc_max, bc_sum;

    int lane = t & 31;
    int warp = t >> 5;

    float mx = qv;
#pragma unroll
    for (int o = 16; o; o >>= 1) mx = fmaxf(mx, __shfl_xor_sync(0xffffffffu, mx, o));
    if (lane == 0) red_max[warp] = mx;
    __syncthreads();
    if (t == 0) {
        float x = red_max[0];
#pragma unroll
        for (int i = 1; i < 8; i++) x = fmaxf(x, red_max[i]);
        bc_max = x;
    }
    __syncthreads();
    float rowmax = bc_max;

    float e = expf(qv - rowmax);
    float sm = e;
#pragma unroll
    for (int o = 16; o; o >>= 1) sm += __shfl_xor_sync(0xffffffffu, sm, o);
    if (lane == 0) red_sum[warp] = sm;
    __syncthreads();
    if (t == 0) {
        float x = red_sum[0];
#pragma unroll
        for (int i = 1; i < 8; i++) x += red_sum[i];
        bc_sum = x;
    }
    __syncthreads();

    g_P[row * NT + t] = e / bc_sum;
}

// ---------------------------------------------------------------------------
// Launch: 8 kernels, graph-capturable, allocation-free.
// Input order (metadata): token_feats, unary_score, mask, transitions,
//                         start_transitions, end_transitions, lengths
// ---------------------------------------------------------------------------
extern "C" void kernel_launch(void* const* d_in, const int* in_sizes, int n_in,
                              void* d_out, int out_size) {
    const float* unary   = (const float*)d_in[1];
    const float* mask    = (const float*)d_in[2];
    const float* trans   = (const float*)d_in[3];
    const float* start_t = (const float*)d_in[4];
    const float* end_t   = (const float*)d_in[5];
    const int*   lengths = (const int*)d_in[6];
    float* out = (float*)d_out;

    build_tcat_kernel<<<1024, 256>>>(trans);

    // initial P = softmax(unary_score * mask)
    combine_kernel<<<NBS, 256>>>(unary, mask, start_t, end_t, lengths, out, 0);

    dim3 gemm_grid(NCAT / 128, NBS / 128);   // (8, 256)
    for (int it = 0; it < 3; ++it) {
        sgemm_kernel<<<gemm_grid, 256>>>();
        int mode = (it == 2) ? 2 : 1;
        combine_kernel<<<NBS, 256>>>(unary, mask, start_t, end_t, lengths, out, mode);
    }
}

// round 7
// speedup vs baseline: 1.8745x; 1.8745x over previous
#include <cuda_runtime.h>
#include <cuda_fp16.h>
#include <math.h>
#include <stdint.h>

// Problem constants
#define NB 32
#define NS 1024
#define NT 256
#define NBS 32768          // NB*NS rows
#define NCAT 1024          // 4*NT concatenated transition columns

// Static device scratch (allocation-free rule: __device__ globals)
__device__ float  g_Y[(size_t)NBS * NCAT];   // P @ Tcat   134.2 MB
__device__ __half g_Ph[NBS * NT];            // hi split of softmax(q)
__device__ __half g_Pl[NBS * NT];            // lo split
__device__ __half g_BhT[NCAT * NT];          // B[n][k] hi  (K-major, i.e. B^T rows)
__device__ __half g_BlT[NCAT * NT];          // B[n][k] lo

// ---------------------------------------------------------------------------
// Build split-B (K-major): Bcat[k][n] stored transposed as BT[n][k]
//   n in [0,256):    T0[k][n]          (left  j=1)
//   n in [256,512):  T1[k][n-256]      (left  j=2)
//   n in [512,768):  T0[n-512][k]      (right j=1)
//   n in [768,1024): T1[n-768][k]      (right j=2)
// transitions layout: [2, 256, 256] row-major
// ---------------------------------------------------------------------------
__global__ void build_b_kernel(const float* __restrict__ trans) {
    int idx = blockIdx.x * blockDim.x + threadIdx.x;   // 0 .. 262143
    int n = idx >> 8;          // 0..1023
    int k = idx & 255;         // 0..255
    float v;
    if (n < 256)       v = trans[k * 256 + n];
    else if (n < 512)  v = trans[65536 + k * 256 + (n - 256)];
    else if (n < 768)  v = trans[(n - 512) * 256 + k];
    else               v = trans[65536 + (n - 768) * 256 + k];
    __half h = __float2half_rn(v);
    __half l = __float2half_rn(v - __half2float(h));
    g_BhT[n * NT + k] = h;
    g_BlT[n * NT + k] = l;
}

// ---------------------------------------------------------------------------
// HMMA GEMM: g_Y[32768,1024] = (Ph+Pl)[32768,256] @ (Bh+Bl)^T
// mma.sync.aligned.m16n8k16.row.col.f32.f16.f16.f32 (baseline PTX, sm_80+).
// Block 128x128, 256 threads = 8 warps (2m x 4n), warp tile 64x32.
// K in 4 chunks of 64 halves (128B rows, XOR-16B swizzle).
// 3 split passes per chunk (Ah*Bh + Al*Bh + Ah*Bl), 3 smem buffers (48KB):
//   b0=Ah, b1=Bh, b2=Al ... then b2 reloaded with Bl.
// ---------------------------------------------------------------------------
#define TILE_BYTES 16384                 // 128 rows x 128 B
#define GEMM_SMEM  (3 * TILE_BYTES)      // 48 KB, under default dyn-smem limit

__device__ __forceinline__ uint32_t lds_u32(const char* p) {
    return *(const uint32_t*)p;
}

__device__ __forceinline__ void mma16816(float* d, uint32_t a0, uint32_t a1,
                                         uint32_t a2, uint32_t a3,
                                         uint32_t b0, uint32_t b1) {
    asm volatile(
        "mma.sync.aligned.m16n8k16.row.col.f32.f16.f16.f32 "
        "{%0,%1,%2,%3}, {%4,%5,%6,%7}, {%8,%9}, {%0,%1,%2,%3};"
        : "+f"(d[0]), "+f"(d[1]), "+f"(d[2]), "+f"(d[3])
        : "r"(a0), "r"(a1), "r"(a2), "r"(a3), "r"(b0), "r"(b1));
}

// One split pass over a 64-half K chunk: 4 ks-steps x (4 m-frags x 4 n-frags)
__device__ __forceinline__ void mma_pass(const char* aB, const char* bB,
                                         float acc[4][4][4],
                                         int wm, int wn, int g, int tg) {
#pragma unroll
    for (int ks = 0; ks < 4; ++ks) {
        int kb = ks * 32 + tg * 4;         // byte offset of k halves
        uint32_t af[4][4];
#pragma unroll
        for (int mf = 0; mf < 4; ++mf) {
            int r0 = wm * 64 + mf * 16 + g;
            uint32_t s0 = (uint32_t)((r0 & 7) << 4);
            uint32_t s1 = (uint32_t)(((r0 + 8) & 7) << 4);
            af[mf][0] = lds_u32(aB + r0 * 128 + ((uint32_t)kb ^ s0));
            af[mf][1] = lds_u32(aB + (r0 + 8) * 128 + ((uint32_t)kb ^ s1));
            af[mf][2] = lds_u32(aB + r0 * 128 + ((uint32_t)(kb + 16) ^ s0));
            af[mf][3] = lds_u32(aB + (r0 + 8) * 128 + ((uint32_t)(kb + 16) ^ s1));
        }
        uint32_t bf[4][2];
#pragma unroll
        for (int nf = 0; nf < 4; ++nf) {
            int nr = wn * 32 + nf * 8 + g;
            uint32_t sn = (uint32_t)((nr & 7) << 4);
            bf[nf][0] = lds_u32(bB + nr * 128 + ((uint32_t)kb ^ sn));
            bf[nf][1] = lds_u32(bB + nr * 128 + ((uint32_t)(kb + 16) ^ sn));
        }
#pragma unroll
        for (int mf = 0; mf < 4; ++mf)
#pragma unroll
            for (int nf = 0; nf < 4; ++nf)
                mma16816(acc[mf][nf], af[mf][0], af[mf][1], af[mf][2],
                         af[mf][3], bf[nf][0], bf[nf][1]);
    }
}

// copy one 128-row x 128B tile from gmem (K-major halves) into swizzled smem
__device__ __forceinline__ void copy_tile(char* dst, const __half* srcBase,
                                          int row0, int k0, int cr, int ch,
                                          uint32_t swrow) {
    const uint4* src = (const uint4*)(srcBase + (size_t)(row0 + cr) * NT + k0);
#pragma unroll
    for (int i = 0; i < 4; ++i) {
        uint32_t col = (uint32_t)(ch + i * 16) ^ swrow;
        *(uint4*)(dst + (uint32_t)(cr * 128) + col) = src[(ch >> 4) + i];
    }
}

__global__ void __launch_bounds__(256) gemm_hmma_kernel() {
    extern __shared__ char smem[];
    char* b0 = smem;                     // Ah
    char* b1 = smem + TILE_BYTES;        // Bh
    char* b2 = smem + 2 * TILE_BYTES;    // Al, then Bl

    int tid  = threadIdx.x;
    int wid  = tid >> 5;
    int lane = tid & 31;
    int wm = wid & 1;          // 0..1 : 64-row half
    int wn = wid >> 1;         // 0..3 : 32-col quarter
    int g  = lane >> 2;        // 0..7
    int tg = lane & 3;         // 0..3

    int m0 = blockIdx.y * 128;
    int n0 = blockIdx.x * 128;

    float acc[4][4][4];
#pragma unroll
    for (int i = 0; i < 4; i++)
#pragma unroll
        for (int j = 0; j < 4; j++)
#pragma unroll
            for (int r = 0; r < 4; r++) acc[i][j][r] = 0.0f;

    // copy role: 2 threads per 128B row, 64B each
    int cr = tid >> 1;                 // row 0..127
    int ch = (tid & 1) * 64;           // byte offset 0 or 64
    uint32_t swrow = (uint32_t)((cr & 7) << 4);

    for (int chunk = 0; chunk < 4; ++chunk) {
        int k0 = chunk * 64;           // half index
        if (chunk) __syncthreads();    // protect b0,b1 from overwrite
        copy_tile(b0, g_Ph,  m0, k0, cr, ch, swrow);
        copy_tile(b1, g_BhT, n0, k0, cr, ch, swrow);
        copy_tile(b2, g_Pl,  m0, k0, cr, ch, swrow);
        __syncthreads();

        mma_pass(b0, b1, acc, wm, wn, g, tg);   // Ah * Bh
        mma_pass(b2, b1, acc, wm, wn, g, tg);   // Al * Bh
        __syncthreads();                        // done reading b2
        copy_tile(b2, g_BlT, n0, k0, cr, ch, swrow);
        __syncthreads();
        mma_pass(b0, b2, acc, wm, wn, g, tg);   // Ah * Bl
    }

    // epilogue: c0={g,2tg}, c1={g,2tg+1}, c2={g+8,2tg}, c3={g+8,2tg+1}
#pragma unroll
    for (int mf = 0; mf < 4; ++mf) {
#pragma unroll
        for (int nf = 0; nf < 4; ++nf) {
            int mrow = m0 + wm * 64 + mf * 16 + g;
            int col  = n0 + wn * 32 + nf * 8 + tg * 2;
            float* p = g_Y + (size_t)mrow * NCAT + col;
            *(float2*)p = make_float2(acc[mf][nf][0], acc[mf][nf][1]);
            *(float2*)(p + (size_t)8 * NCAT) = make_float2(acc[mf][nf][2], acc[mf][nf][3]);
        }
    }
}

// ---------------------------------------------------------------------------
// Combine: warp per row, 8 tags per thread, shuffle-only softmax.
// mode 0: q = unary*mask              -> softmax -> (Ph,Pl)
// mode 1: q = (unary*mask + msg)*mask -> softmax -> (Ph,Pl)
// mode 2: same q -> write to out (final)
// ---------------------------------------------------------------------------
__global__ void __launch_bounds__(256) combine_kernel(
    const float* __restrict__ unary_score,
    const float* __restrict__ mask,
    const float* __restrict__ start_t,   // [2,256]
    const float* __restrict__ end_t,     // [2,256]
    const int*   __restrict__ lengths,   // [32]
    float* __restrict__ out,
    int mode)
{
    int warp = threadIdx.x >> 5;
    int lane = threadIdx.x & 31;
    int row = blockIdx.x * 8 + warp;     // b*NS + s
    int b = row >> 10;
    int s = row & 1023;

    float m = mask[row];
    size_t base = (size_t)row * NT + lane;

    float q[8];
#pragma unroll
    for (int j = 0; j < 8; ++j) q[j] = unary_score[base + j * 32] * m;

    if (mode != 0) {
        float msg[8];
#pragma unroll
        for (int j = 0; j < 8; ++j) msg[j] = 0.0f;
        if (s >= 1) {
            const float* p = g_Y + (size_t)(row - 1) * NCAT + lane;
#pragma unroll
            for (int j = 0; j < 8; ++j) msg[j] += p[j * 32];
        }
        if (s >= 2) {
            const float* p = g_Y + (size_t)(row - 2) * NCAT + 256 + lane;
#pragma unroll
            for (int j = 0; j < 8; ++j) msg[j] += p[j * 32];
        }
        if (s <= NS - 2) {
            const float* p = g_Y + (size_t)(row + 1) * NCAT + 512 + lane;
#pragma unroll
            for (int j = 0; j < 8; ++j) msg[j] += p[j * 32];
        }
        if (s <= NS - 3) {
            const float* p = g_Y + (size_t)(row + 2) * NCAT + 768 + lane;
#pragma unroll
            for (int j = 0; j < 8; ++j) msg[j] += p[j * 32];
        }
        int len = __ldg(&lengths[b]);
        if (s == len - 1) {
#pragma unroll
            for (int j = 0; j < 8; ++j) msg[j] += end_t[lane + j * 32];
        }
        if (s == len - 2) {
#pragma unroll
            for (int j = 0; j < 8; ++j) msg[j] += end_t[256 + lane + j * 32];
        }
        if (s < 2) {
#pragma unroll
            for (int j = 0; j < 8; ++j) msg[j] += start_t[s * 256 + lane + j * 32];
        }
#pragma unroll
        for (int j = 0; j < 8; ++j) q[j] = (q[j] + msg[j]) * m;
    }

    if (mode == 2) {
#pragma unroll
        for (int j = 0; j < 8; ++j) out[base + j * 32] = q[j];
        return;
    }

    // softmax over 256 (8 per thread x 32 lanes), shuffle reductions only
    float mx = q[0];
#pragma unroll
    for (int j = 1; j < 8; ++j) mx = fmaxf(mx, q[j]);
#pragma unroll
    for (int o = 16; o; o >>= 1) mx = fmaxf(mx, __shfl_xor_sync(0xffffffffu, mx, o));

    float e[8];
    float sum = 0.0f;
#pragma unroll
    for (int j = 0; j < 8; ++j) { e[j] = __expf(q[j] - mx); sum += e[j]; }
#pragma unroll
    for (int o = 16; o; o >>= 1) sum += __shfl_xor_sync(0xffffffffu, sum, o);
    float rinv = __frcp_rn(sum);

#pragma unroll
    for (int j = 0; j < 8; ++j) {
        float p = e[j] * rinv;
        __half h = __float2half_rn(p);
        __half l = __float2half_rn(p - __half2float(h));
        g_Ph[base + j * 32] = h;
        g_Pl[base + j * 32] = l;
    }
}

// ---------------------------------------------------------------------------
// Input order: token_feats, unary_score, mask, transitions,
//              start_transitions, end_transitions, lengths
// ---------------------------------------------------------------------------
extern "C" void kernel_launch(void* const* d_in, const int* in_sizes, int n_in,
                              void* d_out, int out_size) {
    const float* unary   = (const float*)d_in[1];
    const float* mask    = (const float*)d_in[2];
    const float* trans   = (const float*)d_in[3];
    const float* start_t = (const float*)d_in[4];
    const float* end_t   = (const float*)d_in[5];
    const int*   lengths = (const int*)d_in[6];
    float* out = (float*)d_out;

    build_b_kernel<<<1024, 256>>>(trans);

    // initial P = softmax(unary * mask)
    combine_kernel<<<NBS / 8, 256>>>(unary, mask, start_t, end_t, lengths, out, 0);

    dim3 gemm_grid(NCAT / 128, NBS / 128);   // (8, 256)
    for (int it = 0; it < 3; ++it) {
        gemm_hmma_kernel<<<gemm_grid, 256, GEMM_SMEM>>>();
        int mode = (it == 2) ? 2 : 1;
        combine_kernel<<<NBS / 8, 256>>>(unary, mask, start_t, end_t, lengths, out, mode);
    }
}

// round 8
// speedup vs baseline: 2.4564x; 1.3104x over previous
#include <cuda_runtime.h>
#include <cuda_fp16.h>
#include <math.h>
#include <stdint.h>

// Problem constants
#define NB 32
#define NS 1024
#define NT 256
#define NBS 32768          // NB*NS rows
#define NCAT 1024          // 4*NT concatenated transition columns

// Static device scratch (allocation-free rule: __device__ globals)
__device__ float  g_Y[(size_t)NBS * NCAT];   // P @ Tcat   134.2 MB
__device__ __half g_Ph[NBS * NT];            // hi split of softmax(q)
__device__ __half g_Pl[NBS * NT];            // lo split
__device__ __half g_BhT[NCAT * NT];          // B[n][k] hi  (K-major, i.e. B^T rows)
__device__ __half g_BlT[NCAT * NT];          // B[n][k] lo

// ---------------------------------------------------------------------------
// Build split-B (K-major): Bcat[k][n] stored transposed as BT[n][k]
//   n in [0,256):    T0[k][n]          (left  j=1)
//   n in [256,512):  T1[k][n-256]      (left  j=2)
//   n in [512,768):  T0[n-512][k]      (right j=1)
//   n in [768,1024): T1[n-768][k]      (right j=2)
// ---------------------------------------------------------------------------
__global__ void build_b_kernel(const float* __restrict__ trans) {
    int idx = blockIdx.x * blockDim.x + threadIdx.x;   // 0 .. 262143
    int n = idx >> 8;          // 0..1023
    int k = idx & 255;         // 0..255
    float v;
    if (n < 256)       v = trans[k * 256 + n];
    else if (n < 512)  v = trans[65536 + k * 256 + (n - 256)];
    else if (n < 768)  v = trans[(n - 512) * 256 + k];
    else               v = trans[65536 + (n - 768) * 256 + k];
    __half h = __float2half_rn(v);
    __half l = __float2half_rn(v - __half2float(h));
    g_BhT[n * NT + k] = h;
    g_BlT[n * NT + k] = l;
}

// ---------------------------------------------------------------------------
// HMMA GEMM: g_Y[32768,1024] = (Ph+Pl)[32768,256] @ (Bh+Bl)^T
// mma.sync.aligned.m16n8k16.row.col.f32.f16.f16.f32.
// Block 128x128, 128 threads = 4 warps (2m x 2n), warp tile 64x64.
// ldmatrix.x4 fragment loads. K in 4 chunks of 64 halves (128B rows,
// XOR-(row&7)<<4 swizzle). 3 split passes per chunk with 3 buffers (48KB):
//   b0=Ah, b1=Bh, b2=Al ... then b2 reloaded with Bl.
// ---------------------------------------------------------------------------
#define TILE_BYTES 16384                 // 128 rows x 128 B
#define GEMM_SMEM  (3 * TILE_BYTES)      // 48 KB, under default dyn-smem limit

__device__ __forceinline__ void mma16816(float* d, uint32_t a0, uint32_t a1,
                                         uint32_t a2, uint32_t a3,
                                         uint32_t b0, uint32_t b1) {
    asm volatile(
        "mma.sync.aligned.m16n8k16.row.col.f32.f16.f16.f32 "
        "{%0,%1,%2,%3}, {%4,%5,%6,%7}, {%8,%9}, {%0,%1,%2,%3};"
        : "+f"(d[0]), "+f"(d[1]), "+f"(d[2]), "+f"(d[3])
        : "r"(a0), "r"(a1), "r"(a2), "r"(a3), "r"(b0), "r"(b1));
}

__device__ __forceinline__ void ldsm_x4(uint32_t addr, uint32_t& r0, uint32_t& r1,
                                        uint32_t& r2, uint32_t& r3) {
    asm volatile("ldmatrix.sync.aligned.m8n8.x4.shared.b16 {%0,%1,%2,%3}, [%4];"
                 : "=r"(r0), "=r"(r1), "=r"(r2), "=r"(r3) : "r"(addr));
}

// One split pass over a 64-half K chunk. Warp tile 64x64:
// 4 m-frags (16 rows) x 8 n-frags (8 cols), 4 k16 steps.
__device__ __forceinline__ void mma_pass(uint32_t aB, uint32_t bB,
                                         float acc[4][8][4],
                                         int wm, int wn, int lane) {
    int lr = lane & 7;
    int quad = lane >> 3;              // 0..3: ldmatrix source-row group
    int rlow = (quad & 1) * 8 + lr;    // row within 16-row frag
    int khb = (quad >> 1) * 16;        // 0 or 16 bytes (k-half)

#pragma unroll
    for (int ks = 0; ks < 4; ++ks) {
        uint32_t kb = (uint32_t)(ks * 32 + khb);
        // A fragments: 4 x ldmatrix.x4
        uint32_t af[4][4];
#pragma unroll
        for (int mf = 0; mf < 4; ++mf) {
            uint32_t row = (uint32_t)(wm * 64 + mf * 16 + rlow);
            uint32_t addr = aB + row * 128 + (kb ^ ((row & 7) << 4));
            ldsm_x4(addr, af[mf][0], af[mf][1], af[mf][2], af[mf][3]);
        }
        // B fragments: 4 x ldmatrix.x4, each covers two 8-col n-frags
        uint32_t bf[8][2];
#pragma unroll
        for (int i = 0; i < 4; ++i) {
            uint32_t row = (uint32_t)(wn * 64 + i * 16 + rlow);
            uint32_t addr = bB + row * 128 + (kb ^ ((row & 7) << 4));
            ldsm_x4(addr, bf[2 * i][0], bf[2 * i + 1][0],
                    bf[2 * i][1], bf[2 * i + 1][1]);
        }
#pragma unroll
        for (int mf = 0; mf < 4; ++mf)
#pragma unroll
            for (int nf = 0; nf < 8; ++nf)
                mma16816(acc[mf][nf], af[mf][0], af[mf][1], af[mf][2],
                         af[mf][3], bf[nf][0], bf[nf][1]);
    }
}

// copy one 128-row x 128B tile gmem -> swizzled smem, coalesced:
// thread t handles (row = t>>3 + 16p, 16B col = (t&7)*16); each warp-wide
// access covers 4 consecutive full 128B rows.
__device__ __forceinline__ void copy_tile(char* dst, const __half* srcBase,
                                          int row0, int k0, int tid) {
    int trow = tid >> 3;
    uint32_t tcol = (uint32_t)((tid & 7) * 16);
#pragma unroll
    for (int p = 0; p < 8; ++p) {
        int row = trow + p * 16;
        uint4 v = *(const uint4*)((const char*)(srcBase + (size_t)(row0 + row) * NT + k0) + tcol);
        *(uint4*)(dst + (uint32_t)(row * 128) + (tcol ^ ((uint32_t)(row & 7) << 4))) = v;
    }
}

__global__ void __launch_bounds__(128, 2) gemm_hmma_kernel() {
    extern __shared__ char smem[];
    char* b0 = smem;                     // Ah
    char* b1 = smem + TILE_BYTES;        // Bh
    char* b2 = smem + 2 * TILE_BYTES;    // Al, then Bl

    uint32_t sb = (uint32_t)__cvta_generic_to_shared(smem);
    uint32_t u0 = sb, u1 = sb + TILE_BYTES, u2 = sb + 2 * TILE_BYTES;

    int tid  = threadIdx.x;
    int wid  = tid >> 5;
    int lane = tid & 31;
    int wm = wid & 1;          // 0..1 : 64-row half
    int wn = wid >> 1;         // 0..1 : 64-col half
    int g  = lane >> 2;        // 0..7
    int tg = lane & 3;         // 0..3

    int m0 = blockIdx.y * 128;
    int n0 = blockIdx.x * 128;

    float acc[4][8][4];
#pragma unroll
    for (int i = 0; i < 4; i++)
#pragma unroll
        for (int j = 0; j < 8; j++)
#pragma unroll
            for (int r = 0; r < 4; r++) acc[i][j][r] = 0.0f;

    for (int chunk = 0; chunk < 4; ++chunk) {
        int k0 = chunk * 64;           // half index
        if (chunk) __syncthreads();    // protect b0,b2 from overwrite
        copy_tile(b0, g_Ph,  m0, k0, tid);
        copy_tile(b1, g_BhT, n0, k0, tid);
        copy_tile(b2, g_Pl,  m0, k0, tid);
        __syncthreads();

        mma_pass(u0, u1, acc, wm, wn, lane);   // Ah * Bh
        mma_pass(u2, u1, acc, wm, wn, lane);   // Al * Bh
        __syncthreads();                       // done reading b2 (Al)
        copy_tile(b2, g_BlT, n0, k0, tid);
        __syncthreads();
        mma_pass(u0, u2, acc, wm, wn, lane);   // Ah * Bl
    }

    // epilogue: per frag c0={g,2tg}, c1={g,2tg+1}, c2={g+8,2tg}, c3={g+8,2tg+1}
#pragma unroll
    for (int mf = 0; mf < 4; ++mf) {
#pragma unroll
        for (int nf = 0; nf < 8; ++nf) {
            int mrow = m0 + wm * 64 + mf * 16 + g;
            int col  = n0 + wn * 64 + nf * 8 + tg * 2;
            float* p = g_Y + (size_t)mrow * NCAT + col;
            *(float2*)p = make_float2(acc[mf][nf][0], acc[mf][nf][1]);
            *(float2*)(p + (size_t)8 * NCAT) = make_float2(acc[mf][nf][2], acc[mf][nf][3]);
        }
    }
}

// ---------------------------------------------------------------------------
// Combine: warp per row, 8 tags per thread, shuffle-only softmax.
// mode 0: q = unary*mask              -> softmax -> (Ph,Pl)
// mode 1: q = (unary*mask + msg)*mask -> softmax -> (Ph,Pl)
// mode 2: same q -> write to out (final)
// ---------------------------------------------------------------------------
__global__ void __launch_bounds__(256) combine_kernel(
    const float* __restrict__ unary_score,
    const float* __restrict__ mask,
    const float* __restrict__ start_t,   // [2,256]
    const float* __restrict__ end_t,     // [2,256]
    const int*   __restrict__ lengths,   // [32]
    float* __restrict__ out,
    int mode)
{
    int warp = threadIdx.x >> 5;
    int lane = threadIdx.x & 31;
    int row = blockIdx.x * 8 + warp;     // b*NS + s
    int b = row >> 10;
    int s = row & 1023;

    float m = mask[row];
    size_t base = (size_t)row * NT + lane;

    float q[8];
#pragma unroll
    for (int j = 0; j < 8; ++j) q[j] = unary_score[base + j * 32] * m;

    if (mode != 0) {
        float msg[8];
#pragma unroll
        for (int j = 0; j < 8; ++j) msg[j] = 0.0f;
        if (s >= 1) {
            const float* p = g_Y + (size_t)(row - 1) * NCAT + lane;
#pragma unroll
            for (int j = 0; j < 8; ++j) msg[j] += p[j * 32];
        }
        if (s >= 2) {
            const float* p = g_Y + (size_t)(row - 2) * NCAT + 256 + lane;
#pragma unroll
            for (int j = 0; j < 8; ++j) msg[j] += p[j * 32];
        }
        if (s <= NS - 2) {
            const float* p = g_Y + (size_t)(row + 1) * NCAT + 512 + lane;
#pragma unroll
            for (int j = 0; j < 8; ++j) msg[j] += p[j * 32];
        }
        if (s <= NS - 3) {
            const float* p = g_Y + (size_t)(row + 2) * NCAT + 768 + lane;
#pragma unroll
            for (int j = 0; j < 8; ++j) msg[j] += p[j * 32];
        }
        int len = __ldg(&lengths[b]);
        if (s == len - 1) {
#pragma unroll
            for (int j = 0; j < 8; ++j) msg[j] += end_t[lane + j * 32];
        }
        if (s == len - 2) {
#pragma unroll
            for (int j = 0; j < 8; ++j) msg[j] += end_t[256 + lane + j * 32];
        }
        if (s < 2) {
#pragma unroll
            for (int j = 0; j < 8; ++j) msg[j] += start_t[s * 256 + lane + j * 32];
        }
#pragma unroll
        for (int j = 0; j < 8; ++j) q[j] = (q[j] + msg[j]) * m;
    }

    if (mode == 2) {
#pragma unroll
        for (int j = 0; j < 8; ++j) out[base + j * 32] = q[j];
        return;
    }

    // softmax over 256 (8 per thread x 32 lanes), shuffle reductions only
    float mx = q[0];
#pragma unroll
    for (int j = 1; j < 8; ++j) mx = fmaxf(mx, q[j]);
#pragma unroll
    for (int o = 16; o; o >>= 1) mx = fmaxf(mx, __shfl_xor_sync(0xffffffffu, mx, o));

    float e[8];
    float sum = 0.0f;
#pragma unroll
    for (int j = 0; j < 8; ++j) { e[j] = __expf(q[j] - mx); sum += e[j]; }
#pragma unroll
    for (int o = 16; o; o >>= 1) sum += __shfl_xor_sync(0xffffffffu, sum, o);
    float rinv = __frcp_rn(sum);

#pragma unroll
    for (int j = 0; j < 8; ++j) {
        float p = e[j] * rinv;
        __half h = __float2half_rn(p);
        __half l = __float2half_rn(p - __half2float(h));
        g_Ph[base + j * 32] = h;
        g_Pl[base + j * 32] = l;
    }
}

// ---------------------------------------------------------------------------
// Input order: token_feats, unary_score, mask, transitions,
//              start_transitions, end_transitions, lengths
// ---------------------------------------------------------------------------
extern "C" void kernel_launch(void* const* d_in, const int* in_sizes, int n_in,
                              void* d_out, int out_size) {
    const float* unary   = (const float*)d_in[1];
    const float* mask    = (const float*)d_in[2];
    const float* trans   = (const float*)d_in[3];
    const float* start_t = (const float*)d_in[4];
    const float* end_t   = (const float*)d_in[5];
    const int*   lengths = (const int*)d_in[6];
    float* out = (float*)d_out;

    build_b_kernel<<<1024, 256>>>(trans);

    // initial P = softmax(unary * mask)
    combine_kernel<<<NBS / 8, 256>>>(unary, mask, start_t, end_t, lengths, out, 0);

    dim3 gemm_grid(NCAT / 128, NBS / 128);   // (8, 256)
    for (int it = 0; it < 3; ++it) {
        gemm_hmma_kernel<<<gemm_grid, 128, GEMM_SMEM>>>();
        int mode = (it == 2) ? 2 : 1;
        combine_kernel<<<NBS / 8, 256>>>(unary, mask, start_t, end_t, lengths, out, mode);
    }
}